// round 16
// baseline (speedup 1.0000x reference)
#include <cuda_runtime.h>
#include <cuda_bf16.h>
#include <cuda_fp16.h>
#include <mma.h>
#include <cstdint>
#include <math.h>

using namespace nvcuda;

// ---------------------------------------------------------------------------
// LiteTracker correlation pyramid, round 13:
//   corr WMMA fp16 single-term + per-warp direct X write (S3 removed) ->
//   MLP1/MLP2 WMMA fp16 single-term + cp.async (byte-identical to R11/R14).
// ---------------------------------------------------------------------------

#define GDIM 7
#define GG 49
#define CDIM 128
#define NPTS 4096
#define NLEV 4
#define KPAD 2432          // 2401 padded to 76*32
#define HDIM 384
#define ODIM 256
#define PPB 8              // points per corr block

// ------------------------------ level geometry -----------------------------
__constant__ int c_H[4]      = {96, 48, 24, 12};
__constant__ int c_W[4]      = {128, 64, 32, 16};
__constant__ int c_pixoff[4] = {0, 12288, 15360, 16128};

// ------------------------------ device scratch -----------------------------
__device__ __align__(16) float g_fmapT[16320 * 128];
__device__ __align__(16) __half g_X[(size_t)NLEV * NPTS * KPAD];
__device__ __align__(16) __half g_W1h[HDIM * KPAD];
__device__ __align__(16) __half g_W2h[ODIM * HDIM];
__device__ __align__(16) __half g_H[(size_t)NLEV * NPTS * HDIM];

// ------------------------------ cp.async helpers ---------------------------
__device__ __forceinline__ uint32_t smem_to_u32(const void* p) {
    uint32_t a;
    asm("{ .reg .u64 t; cvta.to.shared.u64 t, %1; cvt.u32.u64 %0, t; }"
        : "=r"(a) : "l"(p));
    return a;
}
__device__ __forceinline__ void cp16(uint32_t dst, const void* src) {
    asm volatile("cp.async.cg.shared.global [%0], [%1], 16;" :: "r"(dst), "l"(src));
}
#define CP_COMMIT() asm volatile("cp.async.commit_group;" ::: "memory")
#define CP_WAIT0()  asm volatile("cp.async.wait_group 0;" ::: "memory")

// ---------------------------------------------------------------------------
// Kernel T: fmap [128, H, W] -> fmapT [(H*W), 128]
// ---------------------------------------------------------------------------
__global__ void transpose_kernel(const float* __restrict__ src, int HW, int pixoff) {
    __shared__ float tile[32][33];
    int pix0 = blockIdx.x * 32;
    int ch0  = blockIdx.y * 32;
    int tx = threadIdx.x, ty = threadIdx.y;
    int pix = pix0 + tx;
    if (pix < HW) tile[ty][tx] = src[(ch0 + ty) * HW + pix];
    __syncthreads();
    int opix = pix0 + ty;
    int och  = ch0 + tx;
    if (opix < HW) g_fmapT[(size_t)(pixoff + opix) * 128 + och] = tile[tx][ty];
}

// ---------------------------------------------------------------------------
// Weight prep: single fp16
// ---------------------------------------------------------------------------
__global__ void prep_w1_kernel(const float* __restrict__ w1) {
    int idx = blockIdx.x * 256 + threadIdx.x;
    if (idx >= HDIM * KPAD) return;
    int n = idx / KPAD, k = idx % KPAD;
    float v = (k < 2401) ? w1[k * HDIM + n] : 0.0f;
    g_W1h[idx] = __float2half(v);
}

__global__ void prep_w2_kernel(const float* __restrict__ w2) {
    int idx = blockIdx.x * 256 + threadIdx.x;
    if (idx >= ODIM * HDIM) return;
    int n = idx / HDIM, k = idx % HDIM;
    g_W2h[idx] = __float2half(w2[k * ODIM + n]);
}

// ---------------------------------------------------------------------------
// Kernel C (WMMA fp16 single-term): PPB points per block, register-prefetch
// of tfeat. A = gathered features fp16, B = tfeat fp16. C = A*B^T.
// Per-warp fragment staging + direct X writes (no block-wide C stage sync).
// ---------------------------------------------------------------------------
#define CLDS 136                       // 128 + 8 pad (half elems)
#define CTILE (64 * CLDS)              // one 64x128 tile (elems)
#define CORR_TILES_B (2 * CTILE * 2)   // A, B : 34816 bytes
#define CORR_WSTAGE_B (8 * 16 * 32 * 4)  // 8 warps x 16x32 f32 = 16384 bytes
#define CORR_SMEM (CORR_TILES_B + CORR_WSTAGE_B)   // 51200 bytes
#define NCHUNK 7                       // ceil(1568/256) 16B chunks per thread

__global__ __launch_bounds__(256)
void corr_wmma_kernel(const float* __restrict__ coords,
                      const float* __restrict__ tf0, const float* __restrict__ tf1,
                      const float* __restrict__ tf2, const float* __restrict__ tf3) {
    extern __shared__ __align__(16) char csmem[];
    __half* sA = (__half*)csmem;
    __half* sB = sA + CTILE;

    __shared__ int   s_cidx[PPB][GG][4];
    __shared__ float s_cw[PPB][GG][4];

    int n0 = blockIdx.x * PPB;
    int L  = blockIdx.y;
    const float* tf = (L == 0) ? tf0 : (L == 1) ? tf1 : (L == 2) ? tf2 : tf3;

    int t = threadIdx.x;
    int wid = t >> 5, lane = t & 31;
    float* wstage = (float*)(csmem + CORR_TILES_B) + wid * 512;   // 16x32 f32

    for (int idx = t; idx < PPB * GG; idx += 256) {
        int p = idx / GG, s = idx - p * GG;
        float scale = 1.0f / (float)(1 << L);
        float cx = coords[(n0 + p) * 2 + 0] * scale;
        float cy = coords[(n0 + p) * 2 + 1] * scale;
        int h = s / GDIM, w = s % GDIM;
        float fx = cx + (float)(h - 3);
        float fy = cy + (float)(w - 3);
        float x0f = floorf(fx), y0f = floorf(fy);
        float wx = fx - x0f, wy = fy - y0f;
        int x0 = (int)x0f, y0 = (int)y0f;
        int W = c_W[L], Hh = c_H[L];
        int base = c_pixoff[L];
#pragma unroll
        for (int k = 0; k < 4; k++) {
            int xi = x0 + (k & 1);
            int yi = y0 + (k >> 1);
            bool valid = (xi >= 0) && (xi < W) && (yi >= 0) && (yi < Hh);
            float wk = ((k & 1) ? wx : 1.0f - wx) * ((k >> 1) ? wy : 1.0f - wy);
            s_cidx[p][s][k] = valid ? (base + yi * W + xi) * 128 : 0;
            s_cw[p][s][k]   = valid ? wk : 0.0f;
        }
    }

    int ch_row[NCHUNK], ch_seg[NCHUNK];
#pragma unroll
    for (int j = 0; j < NCHUNK; j++) {
        int chunk = t + 256 * j;
        ch_row[j] = chunk >> 5;
        ch_seg[j] = (chunk & 31) * 4;
    }

    float4 pre[NCHUNK];
#pragma unroll
    for (int j = 0; j < NCHUNK; j++) {
        int chunk = t + 256 * j;
        if (chunk < GG * 32)
            pre[j] = *(const float4*)&tf[((size_t)ch_row[j] * NPTS + n0) * 128 + ch_seg[j]];
    }
    __syncthreads();

    int wm = (wid & 3) * 16;     // C row window [wm, wm+16)
    int wn = (wid >> 2) * 32;    // C col window [wn, wn+32)

    for (int p = 0; p < PPB; p++) {
        int n = n0 + p;

        // convert prefetched tfeat -> B tile (fp16)
#pragma unroll
        for (int j = 0; j < NCHUNK; j++) {
            int chunk = t + 256 * j;
            if (chunk < GG * 32) {
                float4 v = pre[j];
                int row = ch_row[j], seg = ch_seg[j];
                __half* b = &sB[row * CLDS + seg];
                b[0] = __float2half(v.x);
                b[1] = __float2half(v.y);
                b[2] = __float2half(v.z);
                b[3] = __float2half(v.w);
            }
        }

        // bilinear gather -> A tile (fp16)
#pragma unroll
        for (int j = 0; j < NCHUNK; j++) {
            int chunk = t + 256 * j;
            if (chunk < GG * 32) {
                int row = ch_row[j], seg = ch_seg[j];
                float4 a = make_float4(0.f, 0.f, 0.f, 0.f);
#pragma unroll
                for (int k = 0; k < 4; k++) {
                    float wk = s_cw[p][row][k];
                    float4 g = *(const float4*)&g_fmapT[s_cidx[p][row][k] + seg];
                    a.x += wk * g.x; a.y += wk * g.y; a.z += wk * g.z; a.w += wk * g.w;
                }
                __half* ah = &sA[row * CLDS + seg];
                ah[0] = __float2half(a.x);
                ah[1] = __float2half(a.y);
                ah[2] = __float2half(a.z);
                ah[3] = __float2half(a.w);
            }
        }
        __syncthreads();   // S1: tiles ready

        // prefetch tfeat for next point (overlaps mma + write below)
        if (p + 1 < PPB) {
#pragma unroll
            for (int j = 0; j < NCHUNK; j++) {
                int chunk = t + 256 * j;
                if (chunk < GG * 32)
                    pre[j] = *(const float4*)
                        &tf[((size_t)ch_row[j] * NPTS + n + 1) * 128 + ch_seg[j]];
            }
        }

        // MMA: C = A*B^T
        wmma::fragment<wmma::accumulator, 16, 16, 16, float> acc[2];
        wmma::fill_fragment(acc[0], 0.0f);
        wmma::fill_fragment(acc[1], 0.0f);
#pragma unroll
        for (int ks = 0; ks < 8; ks++) {
            wmma::fragment<wmma::matrix_a, 16, 16, 16, __half, wmma::row_major> af;
            wmma::load_matrix_sync(af, sA + wm * CLDS + ks * 16, CLDS);
#pragma unroll
            for (int ni = 0; ni < 2; ni++) {
                wmma::fragment<wmma::matrix_b, 16, 16, 16, __half, wmma::col_major> bf;
                wmma::load_matrix_sync(bf, sB + (wn + ni * 16) * CLDS + ks * 16, CLDS);
                wmma::mma_sync(acc[ni], af, bf, acc[ni]);
            }
        }

        // per-warp stage + direct X write (no block sync needed)
#pragma unroll
        for (int ni = 0; ni < 2; ni++)
            wmma::store_matrix_sync(wstage + ni * 16, acc[ni], 32, wmma::mem_row_major);
        __syncwarp();

        size_t xb = ((size_t)L * NPTS + n) * KPAD;
        {
            int r = lane >> 1;            // 0..15
            int cb = (lane & 1) * 16;     // 0 or 16
            int hw = wm + r;
            if (hw < GG) {
#pragma unroll
                for (int u = 0; u < 16; u++) {
                    int ij = wn + cb + u;
                    if (ij < GG)
                        g_X[xb + hw * 49 + ij] = __float2half(wstage[r * 32 + cb + u]);
                }
            }
        }
        if (t < KPAD - 2401)
            g_X[xb + 2401 + t] = __float2half(0.0f);

        __syncthreads();   // S2: all tile reads done before next convert
    }
}

// ---------------------------------------------------------------------------
// WMMA fp16 GEMM, single-term (A*B), cp.async 2-stage pipeline (= R11/R14).
// ---------------------------------------------------------------------------
#define BK 32
#define LDS 40                       // BK + 8 pad (half)
#define TILE_E (128 * LDS)           // elems per tile
#define TILE_B (TILE_E * 2)          // 10240 bytes per tile
#define STAGE_B (2 * TILE_B)         // 20480 bytes per stage
#define MLP_SMEM (2 * STAGE_B)       // 40960 bytes

template <bool MLP1>
__global__ __launch_bounds__(256)
void wmma_gemm_kernel(const float* __restrict__ bias, float* __restrict__ outp) {
    constexpr int KTOT = MLP1 ? KPAD : HDIM;
    constexpr int NIT  = KTOT / BK;

    extern __shared__ __align__(16) __half dsmem[];
    uint32_t su = smem_to_u32(dsmem);

    int t   = threadIdx.x;
    int wid = t >> 5, lane = t & 31;
    int m0  = blockIdx.x * 128;
    int n0  = blockIdx.y * 128;
    int L   = blockIdx.z;

    const __half* Ah = (MLP1 ? g_X : g_H) + ((size_t)L * NPTS + m0) * KTOT;
    const __half* Bh = (MLP1 ? g_W1h : g_W2h) + (size_t)n0 * KTOT;
    const __half* srcs[2] = {Ah, Bh};

    size_t rowoff[2]; uint32_t smbyte[2];
#pragma unroll
    for (int j = 0; j < 2; j++) {
        int p = t + 256 * j;
        int row = p >> 2, seg = p & 3;
        rowoff[j] = (size_t)row * KTOT + seg * 8;
        smbyte[j] = (uint32_t)(row * LDS + seg * 8) * 2;
    }

    wmma::fragment<wmma::accumulator, 16, 16, 16, float> acc[2][4];
#pragma unroll
    for (int mi = 0; mi < 2; mi++)
#pragma unroll
        for (int ni = 0; ni < 4; ni++) wmma::fill_fragment(acc[mi][ni], 0.0f);

    int wm = (wid & 3) * 32;
    int wn = (wid >> 2) * 64;

#pragma unroll
    for (int tile = 0; tile < 2; tile++)
#pragma unroll
        for (int j = 0; j < 2; j++)
            cp16(su + tile * TILE_B + smbyte[j], srcs[tile] + rowoff[j]);
    CP_COMMIT();

    for (int kt = 0; kt < NIT; kt++) {
        CP_WAIT0();
        __syncthreads();

        if (kt + 1 < NIT) {
            int kc = (kt + 1) * BK;
            uint32_t sb = su + ((kt + 1) & 1) * STAGE_B;
#pragma unroll
            for (int tile = 0; tile < 2; tile++)
#pragma unroll
                for (int j = 0; j < 2; j++)
                    cp16(sb + tile * TILE_B + smbyte[j], srcs[tile] + kc + rowoff[j]);
            CP_COMMIT();
        }

        const __half* sbase = dsmem + (kt & 1) * (2 * TILE_E);
        const __half* sA = sbase;
        const __half* sBt = sbase + TILE_E;

#pragma unroll
        for (int kk = 0; kk < 2; kk++) {
            wmma::fragment<wmma::matrix_a, 16, 16, 16, __half, wmma::row_major> af[2];
#pragma unroll
            for (int mi = 0; mi < 2; mi++)
                wmma::load_matrix_sync(af[mi], sA + (wm + mi * 16) * LDS + kk * 16, LDS);
#pragma unroll
            for (int ni = 0; ni < 4; ni++) {
                wmma::fragment<wmma::matrix_b, 16, 16, 16, __half, wmma::col_major> bf;
                wmma::load_matrix_sync(bf, sBt + (wn + ni * 16) * LDS + kk * 16, LDS);
#pragma unroll
                for (int mi = 0; mi < 2; mi++)
                    wmma::mma_sync(acc[mi][ni], af[mi], bf, acc[mi][ni]);
            }
        }
    }
    __syncthreads();

    float* stage = (float*)dsmem + wid * 256;
    int r = lane >> 1;
    int c = (lane & 1) * 8;
#pragma unroll
    for (int mi = 0; mi < 2; mi++)
#pragma unroll
        for (int ni = 0; ni < 4; ni++) {
            wmma::store_matrix_sync(stage, acc[mi][ni], 16, wmma::mem_row_major);
            __syncwarp();
            int grow = m0 + wm + mi * 16 + r;
            int gcol = n0 + wn + ni * 16 + c;
            float v[8];
#pragma unroll
            for (int u = 0; u < 8; u++) {
                float x = stage[r * 16 + c + u] + bias[gcol + u];
                if (MLP1) x = x * normcdff(x);
                v[u] = x;
            }
            if (MLP1) {
                __half h8[8];
#pragma unroll
                for (int u = 0; u < 8; u++) h8[u] = __float2half(v[u]);
                size_t hidx = ((size_t)L * NPTS + grow) * HDIM + gcol;
                *(uint4*)&g_H[hidx] = *(uint4*)h8;
            } else {
                float* dst = &outp[(size_t)grow * 1024 + L * ODIM + gcol];
                *(float4*)dst       = *(float4*)(v);
                *(float4*)(dst + 4) = *(float4*)(v + 4);
            }
            __syncwarp();
        }
}

// ---------------------------------------------------------------------------
// launch
// ---------------------------------------------------------------------------
extern "C" void kernel_launch(void* const* d_in, const int* in_sizes, int n_in,
                              void* d_out, int out_size) {
    (void)out_size;
    const float* fmaps[4] = {nullptr, nullptr, nullptr, nullptr};
    const float* tfeat[4] = {nullptr, nullptr, nullptr, nullptr};
    const float *coords = nullptr, *w1 = nullptr, *b1 = nullptr, *w2 = nullptr, *b2 = nullptr;
    int tc = 0;
    bool seen98 = false;
    for (int i = 0; i < n_in; i++) {
        int s = in_sizes[i];
        const float* p = (const float*)d_in[i];
        if (s == 1572864)       fmaps[0] = p;
        else if (s == 393216)   fmaps[1] = p;
        else if (s == 24576)    fmaps[3] = p;
        else if (s == 25690112) { if (tc < 4) tfeat[tc++] = p; }
        else if (s == 8192)     coords = p;
        else if (s == 921984)   w1 = p;
        else if (s == 384)      b1 = p;
        else if (s == 256)      b2 = p;
        else if (s == 98304)    { if (!seen98) { fmaps[2] = p; seen98 = true; } else w2 = p; }
    }

    static const int hHs[4] = {96, 48, 24, 12};
    static const int hWs[4] = {128, 64, 32, 16};
    static const int hPixOff[4] = {0, 12288, 15360, 16128};

    cudaFuncSetAttribute(corr_wmma_kernel,
                         cudaFuncAttributeMaxDynamicSharedMemorySize, CORR_SMEM);
    cudaFuncSetAttribute(wmma_gemm_kernel<true>,
                         cudaFuncAttributeMaxDynamicSharedMemorySize, MLP_SMEM);
    cudaFuncSetAttribute(wmma_gemm_kernel<false>,
                         cudaFuncAttributeMaxDynamicSharedMemorySize, MLP_SMEM);

    dim3 tb(32, 32);
    for (int L = 0; L < 4; L++) {
        int HW = hHs[L] * hWs[L];
        transpose_kernel<<<dim3((HW + 31) / 32, 4), tb>>>(fmaps[L], HW, hPixOff[L]);
    }

    prep_w1_kernel<<<(HDIM * KPAD + 255) / 256, 256>>>(w1);
    prep_w2_kernel<<<(ODIM * HDIM + 255) / 256, 256>>>(w2);

    corr_wmma_kernel<<<dim3(NPTS / PPB, NLEV), 256, CORR_SMEM>>>(
        coords, tfeat[0], tfeat[1], tfeat[2], tfeat[3]);

    wmma_gemm_kernel<true><<<dim3(NPTS / 128, HDIM / 128, NLEV), 256, MLP_SMEM>>>(
        b1, nullptr);

    wmma_gemm_kernel<false><<<dim3(NPTS / 128, ODIM / 128, NLEV), 256, MLP_SMEM>>>(
        b2, (float*)d_out);
}

// round 17
// speedup vs baseline: 2.3022x; 2.3022x over previous
#include <cuda_runtime.h>
#include <cuda_bf16.h>
#include <cuda_fp16.h>
#include <mma.h>
#include <cstdint>
#include <math.h>

using namespace nvcuda;

// ---------------------------------------------------------------------------
// LiteTracker correlation pyramid, round 14:
//   corr WMMA fp16 single-term, dynamic smem PADDED to 64KB to pin occupancy
//   at 2 CTAs/SM (L1D = 228 - smem; 3 CTAs starves the fmapT gather's L1).
//   MLP1/MLP2 WMMA fp16 single-term + cp.async (= the 410us build).
// ---------------------------------------------------------------------------

#define GDIM 7
#define GG 49
#define CDIM 128
#define NPTS 4096
#define NLEV 4
#define KPAD 2432          // 2401 padded to 76*32
#define HDIM 384
#define ODIM 256
#define PPB 8              // points per corr block

// ------------------------------ level geometry -----------------------------
__constant__ int c_H[4]      = {96, 48, 24, 12};
__constant__ int c_W[4]      = {128, 64, 32, 16};
__constant__ int c_pixoff[4] = {0, 12288, 15360, 16128};

// ------------------------------ device scratch -----------------------------
__device__ __align__(16) float g_fmapT[16320 * 128];
__device__ __align__(16) __half g_X[(size_t)NLEV * NPTS * KPAD];
__device__ __align__(16) __half g_W1h[HDIM * KPAD];
__device__ __align__(16) __half g_W2h[ODIM * HDIM];
__device__ __align__(16) __half g_H[(size_t)NLEV * NPTS * HDIM];

// ------------------------------ cp.async helpers ---------------------------
__device__ __forceinline__ uint32_t smem_to_u32(const void* p) {
    uint32_t a;
    asm("{ .reg .u64 t; cvta.to.shared.u64 t, %1; cvt.u32.u64 %0, t; }"
        : "=r"(a) : "l"(p));
    return a;
}
__device__ __forceinline__ void cp16(uint32_t dst, const void* src) {
    asm volatile("cp.async.cg.shared.global [%0], [%1], 16;" :: "r"(dst), "l"(src));
}
#define CP_COMMIT() asm volatile("cp.async.commit_group;" ::: "memory")
#define CP_WAIT0()  asm volatile("cp.async.wait_group 0;" ::: "memory")

// ---------------------------------------------------------------------------
// Kernel T: fmap [128, H, W] -> fmapT [(H*W), 128]
// ---------------------------------------------------------------------------
__global__ void transpose_kernel(const float* __restrict__ src, int HW, int pixoff) {
    __shared__ float tile[32][33];
    int pix0 = blockIdx.x * 32;
    int ch0  = blockIdx.y * 32;
    int tx = threadIdx.x, ty = threadIdx.y;
    int pix = pix0 + tx;
    if (pix < HW) tile[ty][tx] = src[(ch0 + ty) * HW + pix];
    __syncthreads();
    int opix = pix0 + ty;
    int och  = ch0 + tx;
    if (opix < HW) g_fmapT[(size_t)(pixoff + opix) * 128 + och] = tile[tx][ty];
}

// ---------------------------------------------------------------------------
// Weight prep: single fp16
// ---------------------------------------------------------------------------
__global__ void prep_w1_kernel(const float* __restrict__ w1) {
    int idx = blockIdx.x * 256 + threadIdx.x;
    if (idx >= HDIM * KPAD) return;
    int n = idx / KPAD, k = idx % KPAD;
    float v = (k < 2401) ? w1[k * HDIM + n] : 0.0f;
    g_W1h[idx] = __float2half(v);
}

__global__ void prep_w2_kernel(const float* __restrict__ w2) {
    int idx = blockIdx.x * 256 + threadIdx.x;
    if (idx >= ODIM * HDIM) return;
    int n = idx / HDIM, k = idx % HDIM;
    g_W2h[idx] = __float2half(w2[k * ODIM + n]);
}

// ---------------------------------------------------------------------------
// Kernel C (WMMA fp16 single-term): PPB points per block, register-prefetch
// of tfeat. A = gathered features fp16, B = tfeat fp16. C = A*B^T.
// Dynamic smem padded to 64KB: per-CTA total 78KB > 228/3 -> 2 CTAs/SM,
// keeping ~72KB of L1D for the fmapT gather working set.
// ---------------------------------------------------------------------------
#define CLDS 136                       // 128 + 8 pad (half elems)
#define CTILE (64 * CLDS)              // one 64x128 tile (elems)
#define CORR_TILES_B (2 * CTILE * 2)   // A, B : 34816 bytes
#define CORR_STAGE_B (64 * 68 * 4)     // 17408 bytes
#define CORR_SMEM 65536                // PADDED (used: 52224) -> 2 CTAs/SM
#define NCHUNK 7                       // ceil(1568/256) 16B chunks per thread

__global__ __launch_bounds__(256)
void corr_wmma_kernel(const float* __restrict__ coords,
                      const float* __restrict__ tf0, const float* __restrict__ tf1,
                      const float* __restrict__ tf2, const float* __restrict__ tf3) {
    extern __shared__ __align__(16) char csmem[];
    __half* sA = (__half*)csmem;
    __half* sB = sA + CTILE;
    float* Cstage = (float*)(csmem + CORR_TILES_B);

    __shared__ int   s_cidx[PPB][GG][4];
    __shared__ float s_cw[PPB][GG][4];

    int n0 = blockIdx.x * PPB;
    int L  = blockIdx.y;
    const float* tf = (L == 0) ? tf0 : (L == 1) ? tf1 : (L == 2) ? tf2 : tf3;

    int t = threadIdx.x;
    int wid = t >> 5;

    for (int idx = t; idx < PPB * GG; idx += 256) {
        int p = idx / GG, s = idx - p * GG;
        float scale = 1.0f / (float)(1 << L);
        float cx = coords[(n0 + p) * 2 + 0] * scale;
        float cy = coords[(n0 + p) * 2 + 1] * scale;
        int h = s / GDIM, w = s % GDIM;
        float fx = cx + (float)(h - 3);
        float fy = cy + (float)(w - 3);
        float x0f = floorf(fx), y0f = floorf(fy);
        float wx = fx - x0f, wy = fy - y0f;
        int x0 = (int)x0f, y0 = (int)y0f;
        int W = c_W[L], Hh = c_H[L];
        int base = c_pixoff[L];
#pragma unroll
        for (int k = 0; k < 4; k++) {
            int xi = x0 + (k & 1);
            int yi = y0 + (k >> 1);
            bool valid = (xi >= 0) && (xi < W) && (yi >= 0) && (yi < Hh);
            float wk = ((k & 1) ? wx : 1.0f - wx) * ((k >> 1) ? wy : 1.0f - wy);
            s_cidx[p][s][k] = valid ? (base + yi * W + xi) * 128 : 0;
            s_cw[p][s][k]   = valid ? wk : 0.0f;
        }
    }

    int ch_row[NCHUNK], ch_seg[NCHUNK];
#pragma unroll
    for (int j = 0; j < NCHUNK; j++) {
        int chunk = t + 256 * j;
        ch_row[j] = chunk >> 5;
        ch_seg[j] = (chunk & 31) * 4;
    }

    float4 pre[NCHUNK];
#pragma unroll
    for (int j = 0; j < NCHUNK; j++) {
        int chunk = t + 256 * j;
        if (chunk < GG * 32)
            pre[j] = *(const float4*)&tf[((size_t)ch_row[j] * NPTS + n0) * 128 + ch_seg[j]];
    }
    __syncthreads();

    int wm = (wid & 3) * 16;
    int wn = (wid >> 2) * 32;

    for (int p = 0; p < PPB; p++) {
        int n = n0 + p;

        // convert prefetched tfeat -> B tile (fp16)
#pragma unroll
        for (int j = 0; j < NCHUNK; j++) {
            int chunk = t + 256 * j;
            if (chunk < GG * 32) {
                float4 v = pre[j];
                int row = ch_row[j], seg = ch_seg[j];
                __half* b = &sB[row * CLDS + seg];
                b[0] = __float2half(v.x);
                b[1] = __float2half(v.y);
                b[2] = __float2half(v.z);
                b[3] = __float2half(v.w);
            }
        }

        // bilinear gather -> A tile (fp16); fmapT working set is L1-resident
#pragma unroll
        for (int j = 0; j < NCHUNK; j++) {
            int chunk = t + 256 * j;
            if (chunk < GG * 32) {
                int row = ch_row[j], seg = ch_seg[j];
                float4 a = make_float4(0.f, 0.f, 0.f, 0.f);
#pragma unroll
                for (int k = 0; k < 4; k++) {
                    float wk = s_cw[p][row][k];
                    float4 g = *(const float4*)&g_fmapT[s_cidx[p][row][k] + seg];
                    a.x += wk * g.x; a.y += wk * g.y; a.z += wk * g.z; a.w += wk * g.w;
                }
                __half* ah = &sA[row * CLDS + seg];
                ah[0] = __float2half(a.x);
                ah[1] = __float2half(a.y);
                ah[2] = __float2half(a.z);
                ah[3] = __float2half(a.w);
            }
        }
        __syncthreads();   // S1: tiles ready

        // prefetch tfeat for next point (overlaps mma + write below)
        if (p + 1 < PPB) {
#pragma unroll
            for (int j = 0; j < NCHUNK; j++) {
                int chunk = t + 256 * j;
                if (chunk < GG * 32)
                    pre[j] = *(const float4*)
                        &tf[((size_t)ch_row[j] * NPTS + n + 1) * 128 + ch_seg[j]];
            }
        }

        // MMA: C = A*B^T
        wmma::fragment<wmma::accumulator, 16, 16, 16, float> acc[2];
        wmma::fill_fragment(acc[0], 0.0f);
        wmma::fill_fragment(acc[1], 0.0f);
#pragma unroll
        for (int ks = 0; ks < 8; ks++) {
            wmma::fragment<wmma::matrix_a, 16, 16, 16, __half, wmma::row_major> af;
            wmma::load_matrix_sync(af, sA + wm * CLDS + ks * 16, CLDS);
#pragma unroll
            for (int ni = 0; ni < 2; ni++) {
                wmma::fragment<wmma::matrix_b, 16, 16, 16, __half, wmma::col_major> bf;
                wmma::load_matrix_sync(bf, sB + (wn + ni * 16) * CLDS + ks * 16, CLDS);
                wmma::mma_sync(acc[ni], af, bf, acc[ni]);
            }
        }
        __syncthreads();   // S2

#pragma unroll
        for (int ni = 0; ni < 2; ni++)
            wmma::store_matrix_sync(Cstage + wm * 68 + wn + ni * 16, acc[ni], 68,
                                    wmma::mem_row_major);
        __syncthreads();   // S3

        // write X row (fp16) + zero pad
        size_t xb = ((size_t)L * NPTS + n) * KPAD;
        for (int idx = t; idx < 2401; idx += 256) {
            int hw = idx / 49, ij = idx - hw * 49;
            g_X[xb + idx] = __float2half(Cstage[hw * 68 + ij]);
        }
        if (t < KPAD - 2401)
            g_X[xb + 2401 + t] = __float2half(0.0f);
    }
}

// ---------------------------------------------------------------------------
// WMMA fp16 GEMM, single-term (A*B), cp.async 2-stage pipeline (= 410us build).
// ---------------------------------------------------------------------------
#define BK 32
#define LDS 40                       // BK + 8 pad (half)
#define TILE_E (128 * LDS)           // elems per tile
#define TILE_B (TILE_E * 2)          // 10240 bytes per tile
#define STAGE_B (2 * TILE_B)         // 20480 bytes per stage
#define MLP_SMEM (2 * STAGE_B)       // 40960 bytes

template <bool MLP1>
__global__ __launch_bounds__(256)
void wmma_gemm_kernel(const float* __restrict__ bias, float* __restrict__ outp) {
    constexpr int KTOT = MLP1 ? KPAD : HDIM;
    constexpr int NIT  = KTOT / BK;

    extern __shared__ __align__(16) __half dsmem[];
    uint32_t su = smem_to_u32(dsmem);

    int t   = threadIdx.x;
    int wid = t >> 5, lane = t & 31;
    int m0  = blockIdx.x * 128;
    int n0  = blockIdx.y * 128;
    int L   = blockIdx.z;

    const __half* Ah = (MLP1 ? g_X : g_H) + ((size_t)L * NPTS + m0) * KTOT;
    const __half* Bh = (MLP1 ? g_W1h : g_W2h) + (size_t)n0 * KTOT;
    const __half* srcs[2] = {Ah, Bh};

    size_t rowoff[2]; uint32_t smbyte[2];
#pragma unroll
    for (int j = 0; j < 2; j++) {
        int p = t + 256 * j;
        int row = p >> 2, seg = p & 3;
        rowoff[j] = (size_t)row * KTOT + seg * 8;
        smbyte[j] = (uint32_t)(row * LDS + seg * 8) * 2;
    }

    wmma::fragment<wmma::accumulator, 16, 16, 16, float> acc[2][4];
#pragma unroll
    for (int mi = 0; mi < 2; mi++)
#pragma unroll
        for (int ni = 0; ni < 4; ni++) wmma::fill_fragment(acc[mi][ni], 0.0f);

    int wm = (wid & 3) * 32;
    int wn = (wid >> 2) * 64;

#pragma unroll
    for (int tile = 0; tile < 2; tile++)
#pragma unroll
        for (int j = 0; j < 2; j++)
            cp16(su + tile * TILE_B + smbyte[j], srcs[tile] + rowoff[j]);
    CP_COMMIT();

    for (int kt = 0; kt < NIT; kt++) {
        CP_WAIT0();
        __syncthreads();

        if (kt + 1 < NIT) {
            int kc = (kt + 1) * BK;
            uint32_t sb = su + ((kt + 1) & 1) * STAGE_B;
#pragma unroll
            for (int tile = 0; tile < 2; tile++)
#pragma unroll
                for (int j = 0; j < 2; j++)
                    cp16(sb + tile * TILE_B + smbyte[j], srcs[tile] + kc + rowoff[j]);
            CP_COMMIT();
        }

        const __half* sbase = dsmem + (kt & 1) * (2 * TILE_E);
        const __half* sA = sbase;
        const __half* sBt = sbase + TILE_E;

#pragma unroll
        for (int kk = 0; kk < 2; kk++) {
            wmma::fragment<wmma::matrix_a, 16, 16, 16, __half, wmma::row_major> af[2];
#pragma unroll
            for (int mi = 0; mi < 2; mi++)
                wmma::load_matrix_sync(af[mi], sA + (wm + mi * 16) * LDS + kk * 16, LDS);
#pragma unroll
            for (int ni = 0; ni < 4; ni++) {
                wmma::fragment<wmma::matrix_b, 16, 16, 16, __half, wmma::col_major> bf;
                wmma::load_matrix_sync(bf, sBt + (wn + ni * 16) * LDS + kk * 16, LDS);
#pragma unroll
                for (int mi = 0; mi < 2; mi++)
                    wmma::mma_sync(acc[mi][ni], af[mi], bf, acc[mi][ni]);
            }
        }
    }
    __syncthreads();

    float* stage = (float*)dsmem + wid * 256;
    int r = lane >> 1;
    int c = (lane & 1) * 8;
#pragma unroll
    for (int mi = 0; mi < 2; mi++)
#pragma unroll
        for (int ni = 0; ni < 4; ni++) {
            wmma::store_matrix_sync(stage, acc[mi][ni], 16, wmma::mem_row_major);
            __syncwarp();
            int grow = m0 + wm + mi * 16 + r;
            int gcol = n0 + wn + ni * 16 + c;
            float v[8];
#pragma unroll
            for (int u = 0; u < 8; u++) {
                float x = stage[r * 16 + c + u] + bias[gcol + u];
                if (MLP1) x = x * normcdff(x);
                v[u] = x;
            }
            if (MLP1) {
                __half h8[8];
#pragma unroll
                for (int u = 0; u < 8; u++) h8[u] = __float2half(v[u]);
                size_t hidx = ((size_t)L * NPTS + grow) * HDIM + gcol;
                *(uint4*)&g_H[hidx] = *(uint4*)h8;
            } else {
                float* dst = &outp[(size_t)grow * 1024 + L * ODIM + gcol];
                *(float4*)dst       = *(float4*)(v);
                *(float4*)(dst + 4) = *(float4*)(v + 4);
            }
            __syncwarp();
        }
}

// ---------------------------------------------------------------------------
// launch
// ---------------------------------------------------------------------------
extern "C" void kernel_launch(void* const* d_in, const int* in_sizes, int n_in,
                              void* d_out, int out_size) {
    (void)out_size;
    const float* fmaps[4] = {nullptr, nullptr, nullptr, nullptr};
    const float* tfeat[4] = {nullptr, nullptr, nullptr, nullptr};
    const float *coords = nullptr, *w1 = nullptr, *b1 = nullptr, *w2 = nullptr, *b2 = nullptr;
    int tc = 0;
    bool seen98 = false;
    for (int i = 0; i < n_in; i++) {
        int s = in_sizes[i];
        const float* p = (const float*)d_in[i];
        if (s == 1572864)       fmaps[0] = p;
        else if (s == 393216)   fmaps[1] = p;
        else if (s == 24576)    fmaps[3] = p;
        else if (s == 25690112) { if (tc < 4) tfeat[tc++] = p; }
        else if (s == 8192)     coords = p;
        else if (s == 921984)   w1 = p;
        else if (s == 384)      b1 = p;
        else if (s == 256)      b2 = p;
        else if (s == 98304)    { if (!seen98) { fmaps[2] = p; seen98 = true; } else w2 = p; }
    }

    static const int hHs[4] = {96, 48, 24, 12};
    static const int hWs[4] = {128, 64, 32, 16};
    static const int hPixOff[4] = {0, 12288, 15360, 16128};

    cudaFuncSetAttribute(corr_wmma_kernel,
                         cudaFuncAttributeMaxDynamicSharedMemorySize, CORR_SMEM);
    cudaFuncSetAttribute(wmma_gemm_kernel<true>,
                         cudaFuncAttributeMaxDynamicSharedMemorySize, MLP_SMEM);
    cudaFuncSetAttribute(wmma_gemm_kernel<false>,
                         cudaFuncAttributeMaxDynamicSharedMemorySize, MLP_SMEM);

    dim3 tb(32, 32);
    for (int L = 0; L < 4; L++) {
        int HW = hHs[L] * hWs[L];
        transpose_kernel<<<dim3((HW + 31) / 32, 4), tb>>>(fmaps[L], HW, hPixOff[L]);
    }

    prep_w1_kernel<<<(HDIM * KPAD + 255) / 256, 256>>>(w1);
    prep_w2_kernel<<<(ODIM * HDIM + 255) / 256, 256>>>(w2);

    corr_wmma_kernel<<<dim3(NPTS / PPB, NLEV), 256, CORR_SMEM>>>(
        coords, tfeat[0], tfeat[1], tfeat[2], tfeat[3]);

    wmma_gemm_kernel<true><<<dim3(NPTS / 128, HDIM / 128, NLEV), 256, MLP_SMEM>>>(
        b1, nullptr);

    wmma_gemm_kernel<false><<<dim3(NPTS / 128, ODIM / 128, NLEV), 256, MLP_SMEM>>>(
        b2, (float*)d_out);
}